// round 1
// baseline (speedup 1.0000x reference)
#include <cuda_runtime.h>

#define B_TOTAL 16384
#define NNODES  200
#define NEDGES  800
#define XF      2600
#define FEAT    2800

#define BM 64
#define BN 128
#define KT 16
#define PAD 68            // padded row stride for transposed activation tiles
#define SMEM_FLOATS (2*KT*PAD + 2*KT*BN + 128*PAD + 128*PAD)
#define SMEM_BYTES  (SMEM_FLOATS * 4)

// ---------------- device scratch (no allocations allowed) ----------------
__device__ float g_gbuf[(long)B_TOTAL * NNODES];
__device__ float g_norm_dst[NNODES];
__device__ float g_ew[3];
__device__ float g_gcb;
__device__ int   g_csr_off[NNODES + 1];
__device__ int   g_csr_src[NEDGES];
__device__ float g_csr_w[NEDGES];

// ---------------- packed f32x2 helpers ----------------
__device__ __forceinline__ unsigned long long ffma2(unsigned long long x,
                                                    unsigned long long w,
                                                    unsigned long long a) {
    unsigned long long d;
    asm("fma.rn.f32x2 %0, %1, %2, %3;" : "=l"(d) : "l"(x), "l"(w), "l"(a));
    return d;
}
__device__ __forceinline__ unsigned long long dup2(float x) {
    unsigned long long r;
    asm("mov.b64 %0, {%1, %1};" : "=l"(r) : "f"(x));
    return r;
}
__device__ __forceinline__ float2 unp2(unsigned long long v) {
    float2 r;
    asm("mov.b64 {%0, %1}, %2;" : "=f"(r.x), "=f"(r.y) : "l"(v));
    return r;
}
__device__ __forceinline__ float softplusf(float x) {
    return fmaxf(x, 0.f) + log1pf(expf(-fabsf(x)));
}

// 4 rows x 8 cols (4 col-pairs) FMA micro-tile
#define FMA44(ACC, F4, W01, W23) do {                                          \
    unsigned long long fd_;                                                    \
    fd_ = dup2((F4).x);                                                        \
    ACC[0][0]=ffma2(fd_,(W01).x,ACC[0][0]); ACC[0][1]=ffma2(fd_,(W01).y,ACC[0][1]); \
    ACC[0][2]=ffma2(fd_,(W23).x,ACC[0][2]); ACC[0][3]=ffma2(fd_,(W23).y,ACC[0][3]); \
    fd_ = dup2((F4).y);                                                        \
    ACC[1][0]=ffma2(fd_,(W01).x,ACC[1][0]); ACC[1][1]=ffma2(fd_,(W01).y,ACC[1][1]); \
    ACC[1][2]=ffma2(fd_,(W23).x,ACC[1][2]); ACC[1][3]=ffma2(fd_,(W23).y,ACC[1][3]); \
    fd_ = dup2((F4).z);                                                        \
    ACC[2][0]=ffma2(fd_,(W01).x,ACC[2][0]); ACC[2][1]=ffma2(fd_,(W01).y,ACC[2][1]); \
    ACC[2][2]=ffma2(fd_,(W23).x,ACC[2][2]); ACC[2][3]=ffma2(fd_,(W23).y,ACC[2][3]); \
    fd_ = dup2((F4).w);                                                        \
    ACC[3][0]=ffma2(fd_,(W01).x,ACC[3][0]); ACC[3][1]=ffma2(fd_,(W01).y,ACC[3][1]); \
    ACC[3][2]=ffma2(fd_,(W23).x,ACC[3][2]); ACC[3][3]=ffma2(fd_,(W23).y,ACC[3][3]); \
} while (0)

// ---------------- kernel 1: norms / ew / CSR-by-dst ----------------
__global__ void prep_kernel(const int* __restrict__ es, const int* __restrict__ ed,
                            const float* __restrict__ emb, const float* __restrict__ gcw,
                            const float* __restrict__ gcb) {
    __shared__ int cnto[NNODES];
    __shared__ int cnti[NNODES];
    int tid = threadIdx.x;
    for (int n = tid; n < NNODES; n += blockDim.x) { cnto[n] = 0; cnti[n] = 0; }
    __syncthreads();
    for (int e = tid; e < NEDGES; e += blockDim.x) {
        atomicAdd(&cnto[es[e]], 1);
        atomicAdd(&cnti[ed[e]], 1);
    }
    __syncthreads();
    for (int n = tid; n < NNODES; n += blockDim.x) {
        float dd = (float)max(cnti[n], 1);
        g_norm_dst[n] = 1.0f / sqrtf(dd);
    }
    if (tid < 3) {
        float s = 0.f;
        #pragma unroll
        for (int j = 0; j < 5; j++) s += emb[tid * 5 + j] * gcw[j];
        g_ew[tid] = s;
    }
    if (tid == 0) {
        g_gcb = gcb[0];
        int pos[NNODES];
        int off = 0;
        for (int d = 0; d < NNODES; d++) { g_csr_off[d] = off; pos[d] = off; off += cnti[d]; }
        g_csr_off[NNODES] = off;
        for (int e = 0; e < NEDGES; e++) {
            int d = ed[e];
            int s = es[e];
            int p = pos[d]++;
            g_csr_src[p] = s;
            g_csr_w[p] = 1.0f / sqrtf((float)max(cnto[s], 1));
        }
    }
}

// ---------------- kernel 2: graph conv -> g_gbuf[B][200] ----------------
#define GC_ROWS 8
__global__ __launch_bounds__(256) void gconv_kernel(const int* __restrict__ apps) {
    __shared__ float hw[GC_ROWS][NNODES];
    const int b0 = blockIdx.x * GC_ROWS;
    const int tid = threadIdx.x;
    for (int i = tid; i < GC_ROWS * NNODES; i += 256) {
        int r = i / NNODES, n = i % NNODES;
        hw[r][n] = g_ew[apps[(long)(b0 + r) * NNODES + n]];
    }
    __syncthreads();
    const float gcb = g_gcb;
    for (int i = tid; i < GC_ROWS * NNODES; i += 256) {
        int r = i / NNODES, d = i % NNODES;
        int o0 = g_csr_off[d], o1 = g_csr_off[d + 1];
        float s = 0.f;
        for (int e = o0; e < o1; e++) s += g_csr_w[e] * hw[r][g_csr_src[e]];
        g_gbuf[(long)(b0 + r) * NNODES + d] = g_norm_dst[d] * s + gcb;
    }
}

// ---------------- kernel 3: fused 4-layer MLP ----------------
__global__ __launch_bounds__(256, 2) void mlp_kernel(
    const float* __restrict__ x,
    const float* __restrict__ W1, const float* __restrict__ b1,
    const float* __restrict__ W2, const float* __restrict__ b2,
    const float* __restrict__ W3, const float* __restrict__ b3,
    const float* __restrict__ W4, const float* __restrict__ b4,
    float* __restrict__ out) {

    extern __shared__ float sm[];
    float* xT   = sm;                     // [2][KT][PAD]  feat tile, k-major
    float* sW   = sm + 2 * KT * PAD;      // [2][KT][BN]   weight tile
    float* sA1T = sW + 2 * KT * BN;       // [128][PAD]    a1 transposed (reused as a3T)
    float* sA2T = sA1T + 128 * PAD;       // [128][PAD]    a2 transposed

    const int tid = threadIdx.x;
    const int tx = tid & 15;              // 16 col groups
    const int ty = tid >> 4;              // 16 row groups
    const int b0 = blockIdx.x * BM;

    // loader mapping: each thread loads a float4 of feat for one row
    const int lrow = tid >> 2;            // 0..63
    const int lkq  = (tid & 3) * 4;       // 0,4,8,12
    const long xbase = (long)(b0 + lrow) * XF;
    const long gbase = (long)(b0 + lrow) * NNODES;

    unsigned long long acc[4][4];
    #pragma unroll
    for (int i = 0; i < 4; i++)
        #pragma unroll
        for (int j = 0; j < 4; j++) acc[i][j] = 0ull;

    // ---------- GEMM1: a1 = softplus(feat @ W1 + b1), K=2800 ----------
    float4 fv, wva, wvb;
    {   // prologue: tile 0 (fully inside x)
        fv = *(const float4*)(x + xbase + lkq);
        const float4* wsrc = (const float4*)(W1);
        wva = wsrc[tid]; wvb = wsrc[tid + 256];
        xT[(lkq + 0) * PAD + lrow] = fv.x;
        xT[(lkq + 1) * PAD + lrow] = fv.y;
        xT[(lkq + 2) * PAD + lrow] = fv.z;
        xT[(lkq + 3) * PAD + lrow] = fv.w;
        float4* wdst = (float4*)sW;
        wdst[tid] = wva; wdst[tid + 256] = wvb;
    }

    const int NT1 = FEAT / KT;            // 175
    for (int t = 0; t < NT1; t++) {
        __syncthreads();
        const int cur = t & 1;
        const bool more = (t + 1 < NT1);
        if (more) {
            const int k0 = (t + 1) * KT;
            const int kg = k0 + lkq;
            if (kg + 3 < XF) {
                fv = *(const float4*)(x + xbase + kg);
            } else {
                float tmp[4];
                #pragma unroll
                for (int j = 0; j < 4; j++) {
                    int k = kg + j;
                    tmp[j] = (k < XF) ? x[xbase + k] : g_gbuf[gbase + (k - XF)];
                }
                fv = make_float4(tmp[0], tmp[1], tmp[2], tmp[3]);
            }
            const float4* wsrc = (const float4*)(W1 + (long)k0 * BN);
            wva = wsrc[tid]; wvb = wsrc[tid + 256];
        }
        const float* xt = xT + cur * (KT * PAD);
        const float* wt = sW + cur * (KT * BN);
        #pragma unroll
        for (int kk = 0; kk < KT; kk++) {
            float4 f = *(const float4*)(xt + kk * PAD + ty * 4);
            ulonglong2 w01 = *(const ulonglong2*)(wt + kk * BN + tx * 8);
            ulonglong2 w23 = *(const ulonglong2*)(wt + kk * BN + tx * 8 + 4);
            FMA44(acc, f, w01, w23);
        }
        if (more) {
            const int nb = cur ^ 1;
            float* xtd = xT + nb * (KT * PAD);
            xtd[(lkq + 0) * PAD + lrow] = fv.x;
            xtd[(lkq + 1) * PAD + lrow] = fv.y;
            xtd[(lkq + 2) * PAD + lrow] = fv.z;
            xtd[(lkq + 3) * PAD + lrow] = fv.w;
            float4* wdst = (float4*)(sW + nb * (KT * BN));
            wdst[tid] = wva; wdst[tid + 256] = wvb;
        }
    }
    // epilogue 1: softplus + bias, store transposed
    #pragma unroll
    for (int i = 0; i < 4; i++) {
        const int r = ty * 4 + i;
        #pragma unroll
        for (int cp = 0; cp < 4; cp++) {
            float2 v = unp2(acc[i][cp]);
            const int c = tx * 8 + cp * 2;
            sA1T[(c    ) * PAD + r] = softplusf(v.x + b1[c]);
            sA1T[(c + 1) * PAD + r] = softplusf(v.y + b1[c + 1]);
        }
    }
    __syncthreads();   // all GEMM1 work & a1 stores done

    // ---------- GEMM2: a2 = softplus(a1 @ W2 + b2), K=128 ----------
    #pragma unroll
    for (int i = 0; i < 4; i++)
        #pragma unroll
        for (int j = 0; j < 4; j++) acc[i][j] = 0ull;
    {
        const float4* wsrc = (const float4*)(W2);
        wva = wsrc[tid]; wvb = wsrc[tid + 256];
        float4* wdst = (float4*)sW;
        wdst[tid] = wva; wdst[tid + 256] = wvb;
    }
    for (int t = 0; t < 8; t++) {
        __syncthreads();
        const int cur = t & 1;
        const bool more = (t < 7);
        if (more) {
            const float4* wsrc = (const float4*)(W2 + (long)(t + 1) * KT * BN);
            wva = wsrc[tid]; wvb = wsrc[tid + 256];
        }
        const float* at = sA1T + t * KT * PAD;
        const float* wt = sW + cur * (KT * BN);
        #pragma unroll
        for (int kk = 0; kk < KT; kk++) {
            float4 f = *(const float4*)(at + kk * PAD + ty * 4);
            ulonglong2 w01 = *(const ulonglong2*)(wt + kk * BN + tx * 8);
            ulonglong2 w23 = *(const ulonglong2*)(wt + kk * BN + tx * 8 + 4);
            FMA44(acc, f, w01, w23);
        }
        if (more) {
            float4* wdst = (float4*)(sW + (cur ^ 1) * (KT * BN));
            wdst[tid] = wva; wdst[tid + 256] = wvb;
        }
    }
    #pragma unroll
    for (int i = 0; i < 4; i++) {
        const int r = ty * 4 + i;
        #pragma unroll
        for (int cp = 0; cp < 4; cp++) {
            float2 v = unp2(acc[i][cp]);
            const int c = tx * 8 + cp * 2;
            sA2T[(c    ) * PAD + r] = softplusf(v.x + b2[c]);
            sA2T[(c + 1) * PAD + r] = softplusf(v.y + b2[c + 1]);
        }
    }
    __syncthreads();

    // ---------- GEMM3: a3 = tanhshrink(a2 @ W3 + b3), K=128, N=64 ----------
    unsigned long long acc3[4][2];
    #pragma unroll
    for (int i = 0; i < 4; i++) { acc3[i][0] = 0ull; acc3[i][1] = 0ull; }
    float4 w3v;
    {
        const float4* wsrc = (const float4*)(W3);
        w3v = wsrc[tid];
        ((float4*)sW)[tid] = w3v;
    }
    for (int t = 0; t < 8; t++) {
        __syncthreads();
        const int cur = t & 1;
        const bool more = (t < 7);
        if (more) {
            const float4* wsrc = (const float4*)(W3 + (long)(t + 1) * KT * 64);
            w3v = wsrc[tid];
        }
        const float* at = sA2T + t * KT * PAD;
        const float* wt = sW + cur * (KT * BN);   // holds [KT][64]
        #pragma unroll
        for (int kk = 0; kk < KT; kk++) {
            float4 f = *(const float4*)(at + kk * PAD + ty * 4);
            ulonglong2 w01 = *(const ulonglong2*)(wt + kk * 64 + tx * 4);
            unsigned long long fd;
            fd = dup2(f.x);
            acc3[0][0] = ffma2(fd, w01.x, acc3[0][0]);
            acc3[0][1] = ffma2(fd, w01.y, acc3[0][1]);
            fd = dup2(f.y);
            acc3[1][0] = ffma2(fd, w01.x, acc3[1][0]);
            acc3[1][1] = ffma2(fd, w01.y, acc3[1][1]);
            fd = dup2(f.z);
            acc3[2][0] = ffma2(fd, w01.x, acc3[2][0]);
            acc3[2][1] = ffma2(fd, w01.y, acc3[2][1]);
            fd = dup2(f.w);
            acc3[3][0] = ffma2(fd, w01.x, acc3[3][0]);
            acc3[3][1] = ffma2(fd, w01.y, acc3[3][1]);
        }
        if (more) {
            ((float4*)(sW + (cur ^ 1) * (KT * BN)))[tid] = w3v;
        }
    }
    // epilogue 3: tanhshrink, store transposed into sA1T region (a3T[64][PAD])
    #pragma unroll
    for (int i = 0; i < 4; i++) {
        const int r = ty * 4 + i;
        #pragma unroll
        for (int cp = 0; cp < 2; cp++) {
            float2 v = unp2(acc3[i][cp]);
            const int c = tx * 4 + cp * 2;
            float a0 = v.x + b3[c];
            float a1 = v.y + b3[c + 1];
            sA1T[(c    ) * PAD + r] = a0 - tanhf(a0);
            sA1T[(c + 1) * PAD + r] = a1 - tanhf(a1);
        }
    }
    __syncthreads();

    // ---------- GEMM4 + sigmoid: out = sigmoid(a3 @ W4 + b4), N=2 ----------
    if (tid < 128) {
        const int r = tid >> 1;
        const int c = tid & 1;
        float s = b4[c];
        #pragma unroll
        for (int k = 0; k < 64; k++) s += sA1T[k * PAD + r] * W4[k * 2 + c];
        out[(long)(b0 + r) * 2 + c] = 1.f / (1.f + expf(-s));
    }
}

// ---------------- launch ----------------
extern "C" void kernel_launch(void* const* d_in, const int* in_sizes, int n_in,
                              void* d_out, int out_size) {
    const float* x    = (const float*)d_in[0];
    const int*   apps = (const int*)d_in[1];
    const int*   es   = (const int*)d_in[2];
    const int*   ed   = (const int*)d_in[3];
    const float* emb  = (const float*)d_in[4];
    const float* gcw  = (const float*)d_in[5];
    const float* gcb  = (const float*)d_in[6];
    const float* W1   = (const float*)d_in[7];
    const float* b1   = (const float*)d_in[8];
    const float* W2   = (const float*)d_in[9];
    const float* b2   = (const float*)d_in[10];
    const float* W3   = (const float*)d_in[11];
    const float* b3   = (const float*)d_in[12];
    const float* W4   = (const float*)d_in[13];
    const float* b4   = (const float*)d_in[14];
    float* out = (float*)d_out;

    cudaFuncSetAttribute(mlp_kernel, cudaFuncAttributeMaxDynamicSharedMemorySize, SMEM_BYTES);

    prep_kernel<<<1, 256>>>(es, ed, emb, gcw, gcb);
    gconv_kernel<<<B_TOTAL / GC_ROWS, 256>>>(apps);
    mlp_kernel<<<B_TOTAL / BM, 256, SMEM_BYTES>>>(x, W1, b1, W2, b2, W3, b3, W4, b4, out);
}

// round 3
// speedup vs baseline: 1.8354x; 1.8354x over previous
#include <cuda_runtime.h>
#include <cuda_bf16.h>
#include <cstdint>

#define B_TOTAL 16384
#define NNODES  200
#define NEDGES  800
#define XF      2600
#define FEATR   2800
#define FEATP   2816          // K padded to 44*64
#define BM      128
#define NT1     (FEATP / 64)  // 44

// ---------------- device scratch ----------------
__device__ __align__(16) float g_gbuf[(size_t)B_TOTAL * NNODES];
__device__ float g_norm_dst[NNODES];
__device__ float g_ew[3];
__device__ float g_gcb;
__device__ int   g_csr_off[NNODES + 1];
__device__ int   g_csr_src[NEDGES];
__device__ float g_csr_w[NEDGES];
__device__ __align__(16) __nv_bfloat16 g_w1t_hi[128 * FEATP];
__device__ __align__(16) __nv_bfloat16 g_w1t_lo[128 * FEATP];
__device__ __align__(16) __nv_bfloat16 g_w2t_hi[128 * 128];
__device__ __align__(16) __nv_bfloat16 g_w2t_lo[128 * 128];
__device__ __align__(16) __nv_bfloat16 g_w3t_hi[64 * 128];
__device__ __align__(16) __nv_bfloat16 g_w3t_lo[64 * 128];

// ---------------- helpers ----------------
__device__ __forceinline__ uint32_t smem_to_u32(const void* p) {
    uint32_t a;
    asm("{ .reg .u64 t; cvta.to.shared.u64 t, %1; cvt.u32.u64 %0, t; }" : "=r"(a) : "l"(p));
    return a;
}
#define SWZ(off) ((off) ^ (((off) >> 3) & 0x70))

__device__ __forceinline__ void ldsm4(uint32_t r[4], uint32_t addr) {
    asm volatile("ldmatrix.sync.aligned.m8n8.x4.shared.b16 {%0,%1,%2,%3}, [%4];"
                 : "=r"(r[0]), "=r"(r[1]), "=r"(r[2]), "=r"(r[3]) : "r"(addr));
}
__device__ __forceinline__ void mma16816(float c[4], const uint32_t a[4],
                                         uint32_t b0, uint32_t b1) {
    asm volatile("mma.sync.aligned.m16n8k16.row.col.f32.bf16.bf16.f32 "
                 "{%0,%1,%2,%3}, {%4,%5,%6,%7}, {%8,%9}, {%0,%1,%2,%3};"
                 : "+f"(c[0]), "+f"(c[1]), "+f"(c[2]), "+f"(c[3])
                 : "r"(a[0]), "r"(a[1]), "r"(a[2]), "r"(a[3]), "r"(b0), "r"(b1));
}
__device__ __forceinline__ void cpa16(uint32_t dst, const void* src) {
    asm volatile("cp.async.cg.shared.global [%0], [%1], 16;" :: "r"(dst), "l"(src));
}
#define CPA_COMMIT() asm volatile("cp.async.commit_group;" ::: "memory")
#define CPA_WAIT0()  asm volatile("cp.async.wait_group 0;" ::: "memory")

__device__ __forceinline__ uint32_t pack_bf16x2(float even, float odd) {
    uint32_t r;
    asm("cvt.rn.bf16x2.f32 %0, %1, %2;" : "=r"(r) : "f"(odd), "f"(even));
    return r;
}
__device__ __forceinline__ void split2(float a, float b, uint32_t& hi2, uint32_t& lo2) {
    hi2 = pack_bf16x2(a, b);
    float ah = __uint_as_float(hi2 << 16);
    float bh = __uint_as_float(hi2 & 0xFFFF0000u);
    lo2 = pack_bf16x2(a - ah, b - bh);
}
__device__ __forceinline__ float softplusf(float x) {
    return fmaxf(x, 0.f) + log1pf(expf(-fabsf(x)));
}

// ---------------- smem layout (bytes) ----------------
#define OFF_B1   0          // 128 f
#define OFF_B2   512
#define OFF_B3   1024       // 64 f
#define OFF_B4   1280       // 2 f
#define OFF_W4   1536       // 128 f
#define OFF_A    2048       // A hi[2],lo[2]: 4 x 16KB
#define OFF_BW   67584      // B hi[2],lo[2]: 4 x 16KB
#define OFF_T    133120     // T hi[2],lo[2]: 4 x 16KB ; reused as fp32 a3[128][68]
#define SMEM_BYTES 198656

// ---------------- prep kernels ----------------
__global__ void prep_graph(const int* __restrict__ es, const int* __restrict__ ed,
                           const float* __restrict__ emb, const float* __restrict__ gcw,
                           const float* __restrict__ gcb) {
    __shared__ int cnto[NNODES], cnti[NNODES], pos[NNODES];
    int tid = threadIdx.x;
    for (int n = tid; n < NNODES; n += 256) { cnto[n] = 0; cnti[n] = 0; }
    __syncthreads();
    for (int e = tid; e < NEDGES; e += 256) {
        atomicAdd(&cnto[es[e]], 1);
        atomicAdd(&cnti[ed[e]], 1);
    }
    __syncthreads();
    for (int n = tid; n < NNODES; n += 256)
        g_norm_dst[n] = rsqrtf((float)max(cnti[n], 1));
    if (tid < 3) {
        float s = 0.f;
        #pragma unroll
        for (int j = 0; j < 5; j++) s += emb[tid * 5 + j] * gcw[j];
        g_ew[tid] = s;
    }
    if (tid == 0) {
        g_gcb = gcb[0];
        int off = 0;
        for (int d = 0; d < NNODES; d++) { g_csr_off[d] = off; pos[d] = off; off += cnti[d]; }
        g_csr_off[NNODES] = off;
    }
    __syncthreads();
    for (int e = tid; e < NEDGES; e += 256) {
        int d = ed[e], s = es[e];
        int p = atomicAdd(&pos[d], 1);
        g_csr_src[p] = s;
        g_csr_w[p] = rsqrtf((float)max(cnto[s], 1));
    }
}

__global__ void prep_weights(const float* __restrict__ W1, const float* __restrict__ W2,
                             const float* __restrict__ W3) {
    const int T1 = 128 * FEATP, T2 = 128 * 128, T3 = 64 * 128;
    for (int i = blockIdx.x * blockDim.x + threadIdx.x; i < T1 + T2 + T3;
         i += gridDim.x * blockDim.x) {
        float v;
        __nv_bfloat16 *ph, *pl;
        if (i < T1) {
            int k = i % FEATP;
            int n = i / FEATP;
            v = (k < FEATR) ? W1[(size_t)k * 128 + n] : 0.f;
            ph = g_w1t_hi + i; pl = g_w1t_lo + i;
        } else if (i < T1 + T2) {
            int j = i - T1;
            int n = j >> 7, k = j & 127;
            v = W2[k * 128 + n];
            ph = g_w2t_hi + j; pl = g_w2t_lo + j;
        } else {
            int j = i - T1 - T2;
            int n = j >> 7, k = j & 127;
            v = W3[k * 64 + n];
            ph = g_w3t_hi + j; pl = g_w3t_lo + j;
        }
        __nv_bfloat16 h = __float2bfloat16(v);
        *ph = h;
        *pl = __float2bfloat16(v - __bfloat162float(h));
    }
}

#define GC_ROWS 8
__global__ __launch_bounds__(256) void gconv_kernel(const int* __restrict__ apps) {
    __shared__ float hw[GC_ROWS][NNODES];
    const int b0 = blockIdx.x * GC_ROWS;
    const int tid = threadIdx.x;
    for (int i = tid; i < GC_ROWS * NNODES; i += 256) {
        int r = i / NNODES, n = i % NNODES;
        hw[r][n] = g_ew[apps[(size_t)(b0 + r) * NNODES + n]];
    }
    __syncthreads();
    const float gcb = g_gcb;
    for (int i = tid; i < GC_ROWS * NNODES; i += 256) {
        int r = i / NNODES, d = i % NNODES;
        int o0 = g_csr_off[d], o1 = g_csr_off[d + 1];
        float s = 0.f;
        for (int e = o0; e < o1; e++) s += g_csr_w[e] * hw[r][g_csr_src[e]];
        g_gbuf[(size_t)(b0 + r) * NNODES + d] = g_norm_dst[d] * s + gcb;
    }
}

// ---------------- loaders ----------------
// A chunk: 128 rows x 64 k fp32 -> split bf16 hi/lo, swizzled 128B rows
__device__ __forceinline__ void load_A_chunk(const float* __restrict__ x, size_t xrow,
                                             size_t grow, int k0, char* Ah, char* Al, int tid) {
    const int row = tid >> 1;
    const int kq0 = (tid & 1) * 32;
    #pragma unroll
    for (int j = 0; j < 8; j++) {
        const int kl = kq0 + j * 4;
        const int k = k0 + kl;
        float4 fv;
        if (k + 3 < XF)        fv = *(const float4*)(x + xrow + k);
        else if (k < FEATR)    fv = *(const float4*)(g_gbuf + grow + (k - XF));
        else                   fv = make_float4(0.f, 0.f, 0.f, 0.f);
        uint32_t h01, l01, h23, l23;
        split2(fv.x, fv.y, h01, l01);
        split2(fv.z, fv.w, h23, l23);
        const uint32_t off = SWZ((uint32_t)(row * 128 + kl * 2));
        *(uint2*)(Ah + off) = make_uint2(h01, h23);
        *(uint2*)(Al + off) = make_uint2(l01, l23);
    }
}

// B tile via cp.async: nrows x 64 k bf16 (already split in global), swizzled
__device__ __forceinline__ void cpa_B_tile(const __nv_bfloat16* __restrict__ W, int ldk,
                                           int k0, uint32_t dst, int nrows, int tid) {
    const int nv = nrows * 8;
    for (int v = tid; v < nv; v += 256) {
        const int n = v >> 3, kq = (v & 7) * 8;
        cpa16(dst + SWZ((uint32_t)(n * 128 + kq * 2)), W + (size_t)n * ldk + k0 + kq);
    }
}

// ---------------- MMA chunk: warp tile 32 x (NTILES*8), K=64 ----------------
template<int NTILES>
__device__ __forceinline__ void mma_chunk(float (&C)[2][NTILES][4],
                                          uint32_t a_hi, uint32_t a_lo,
                                          uint32_t b_hi, uint32_t b_lo,
                                          int wm_base, int wn_base, int lane) {
    const int lr = (lane & 7) + ((lane >> 3) & 1) * 8;
    const int lh = (lane >> 4) * 16;
    #pragma unroll
    for (int kk = 0; kk < 4; kk++) {
        uint32_t ah[2][4], al[2][4];
        #pragma unroll
        for (int mt = 0; mt < 2; mt++) {
            uint32_t off = SWZ((uint32_t)((wm_base + mt * 16 + lr) * 128 + kk * 32 + lh));
            ldsm4(ah[mt], a_hi + off);
            ldsm4(al[mt], a_lo + off);
        }
        #pragma unroll
        for (int ng = 0; ng < NTILES / 2; ng++) {
            uint32_t off = SWZ((uint32_t)((wn_base + ng * 16 + lr) * 128 + kk * 32 + lh));
            uint32_t bh[4], bl[4];
            ldsm4(bh, b_hi + off);
            ldsm4(bl, b_lo + off);
            #pragma unroll
            for (int half = 0; half < 2; half++) {
                const int nt = ng * 2 + half;
                #pragma unroll
                for (int mt = 0; mt < 2; mt++) {
                    mma16816(C[mt][nt], ah[mt], bh[half], bh[half + 2]);
                    mma16816(C[mt][nt], ah[mt], bl[half], bl[half + 2]);
                    mma16816(C[mt][nt], al[mt], bh[half], bh[half + 2]);
                }
            }
        }
    }
}

// epilogue: bias + softplus, split-store to hi/lo chunked tiles ([m][k] layout)
__device__ __forceinline__ void epi_split(float (&C)[2][8][4], const float* bias,
                                          char* dhi, char* dlo,
                                          int wm_base, int wn_base, int lane) {
    const int r0 = wm_base + (lane >> 2);
    const int c0 = wn_base + (lane & 3) * 2;
    #pragma unroll
    for (int mt = 0; mt < 2; mt++) {
        #pragma unroll
        for (int nt = 0; nt < 8; nt++) {
            const int n = c0 + nt * 8;
            const int chunk = n >> 6, col = n & 63;
            const float b0 = bias[n], b1 = bias[n + 1];
            char* th = dhi + chunk * 16384;
            char* tl = dlo + chunk * 16384;
            {
                float v0 = softplusf(C[mt][nt][0] + b0);
                float v1 = softplusf(C[mt][nt][1] + b1);
                uint32_t h, l;
                split2(v0, v1, h, l);
                const uint32_t off = SWZ((uint32_t)((r0 + mt * 16) * 128 + col * 2));
                *(uint32_t*)(th + off) = h;
                *(uint32_t*)(tl + off) = l;
            }
            {
                float v0 = softplusf(C[mt][nt][2] + b0);
                float v1 = softplusf(C[mt][nt][3] + b1);
                uint32_t h, l;
                split2(v0, v1, h, l);
                const uint32_t off = SWZ((uint32_t)((r0 + mt * 16 + 8) * 128 + col * 2));
                *(uint32_t*)(th + off) = h;
                *(uint32_t*)(tl + off) = l;
            }
        }
    }
}

// ---------------- fused MLP kernel ----------------
__global__ __launch_bounds__(256, 1)
void mlp_kernel(const float* __restrict__ x,
                const float* __restrict__ b1g, const float* __restrict__ b2g,
                const float* __restrict__ b3g, const float* __restrict__ b4g,
                const float* __restrict__ W4g, float* __restrict__ out) {
    extern __shared__ char sm[];
    const uint32_t su = smem_to_u32(sm);
    const int tid = threadIdx.x;
    const int wid = tid >> 5;
    const int lane = tid & 31;
    const int b0 = blockIdx.x * BM;

    float* sb1 = (float*)(sm + OFF_B1);
    float* sb2 = (float*)(sm + OFF_B2);
    float* sb3 = (float*)(sm + OFF_B3);
    float* sb4 = (float*)(sm + OFF_B4);
    float* sW4 = (float*)(sm + OFF_W4);
    if (tid < 128) { sb1[tid] = b1g[tid]; sb2[tid] = b2g[tid]; sW4[tid] = W4g[tid]; }
    if (tid < 64) sb3[tid] = b3g[tid];
    if (tid < 2) sb4[tid] = b4g[tid];

    // smem buffer addresses
    char* pAh[2] = { sm + OFF_A,          sm + OFF_A + 16384 };
    char* pAl[2] = { sm + OFF_A + 32768,  sm + OFF_A + 49152 };
    const uint32_t uAh[2] = { su + OFF_A,         su + OFF_A + 16384 };
    const uint32_t uAl[2] = { su + OFF_A + 32768, su + OFF_A + 49152 };
    const uint32_t uBh[2] = { su + OFF_BW,         su + OFF_BW + 16384 };
    const uint32_t uBl[2] = { su + OFF_BW + 32768, su + OFF_BW + 49152 };
    char* pTh[2] = { sm + OFF_T,          sm + OFF_T + 16384 };
    char* pTl[2] = { sm + OFF_T + 32768,  sm + OFF_T + 49152 };
    const uint32_t uTh[2] = { su + OFF_T,         su + OFF_T + 16384 };
    const uint32_t uTl[2] = { su + OFF_T + 32768, su + OFF_T + 49152 };

    const size_t xrow = (size_t)(b0 + (tid >> 1)) * XF;
    const size_t grow = (size_t)(b0 + (tid >> 1)) * NNODES;

    const int wm = (wid >> 1) * 32;   // 4 row groups of 32
    const int wn = (wid & 1) * 64;    // 2 col groups of 64

    float C[2][8][4];
    #pragma unroll
    for (int i = 0; i < 2; i++)
        #pragma unroll
        for (int j = 0; j < 8; j++)
            #pragma unroll
            for (int q = 0; q < 4; q++) C[i][j][q] = 0.f;

    // -------- GEMM1: feat[128x2816] @ W1t -> C, pipelined --------
    load_A_chunk(x, xrow, grow, 0, pAh[0], pAl[0], tid);
    cpa_B_tile(g_w1t_hi, FEATP, 0, uBh[0], 128, tid);
    cpa_B_tile(g_w1t_lo, FEATP, 0, uBl[0], 128, tid);
    CPA_COMMIT();

    for (int t = 0; t < NT1; t++) {
        const int cur = t & 1;
        CPA_WAIT0();
        __syncthreads();
        if (t + 1 < NT1) {
            const int nb = cur ^ 1;
            const int k0 = (t + 1) * 64;
            load_A_chunk(x, xrow, grow, k0, pAh[nb], pAl[nb], tid);
            cpa_B_tile(g_w1t_hi, FEATP, k0, uBh[nb], 128, tid);
            cpa_B_tile(g_w1t_lo, FEATP, k0, uBl[nb], 128, tid);
            CPA_COMMIT();
        }
        mma_chunk<8>(C, uAh[cur], uAl[cur], uBh[cur], uBl[cur], wm, wn, lane);
    }
    // epilogue 1: a1 = softplus(C + b1) -> T tiles (hi/lo, 2 chunks)
    epi_split(C, sb1, sm + OFF_T, sm + OFF_T + 32768, wm, wn, lane);
    __syncthreads();

    // -------- GEMM2: a1[128x128] @ W2t --------
    cpa_B_tile(g_w2t_hi, 128, 0,  uBh[0], 128, tid);
    cpa_B_tile(g_w2t_hi, 128, 64, uBh[1], 128, tid);
    cpa_B_tile(g_w2t_lo, 128, 0,  uBl[0], 128, tid);
    cpa_B_tile(g_w2t_lo, 128, 64, uBl[1], 128, tid);
    CPA_COMMIT();
    CPA_WAIT0();
    __syncthreads();

    #pragma unroll
    for (int i = 0; i < 2; i++)
        #pragma unroll
        for (int j = 0; j < 8; j++)
            #pragma unroll
            for (int q = 0; q < 4; q++) C[i][j][q] = 0.f;
    #pragma unroll
    for (int c = 0; c < 2; c++)
        mma_chunk<8>(C, uTh[c], uTl[c], uBh[c], uBl[c], wm, wn, lane);
    // epilogue 2: a2 -> A tiles
    epi_split(C, sb2, sm + OFF_A, sm + OFF_A + 32768, wm, wn, lane);
    __syncthreads();

    // -------- GEMM3: a2[128x128] @ W3t (N=64) --------
    cpa_B_tile(g_w3t_hi, 128, 0,  uBh[0], 64, tid);
    cpa_B_tile(g_w3t_hi, 128, 64, uBh[1], 64, tid);
    cpa_B_tile(g_w3t_lo, 128, 0,  uBl[0], 64, tid);
    cpa_B_tile(g_w3t_lo, 128, 64, uBl[1], 64, tid);
    CPA_COMMIT();
    CPA_WAIT0();
    __syncthreads();

    const int wm3 = (wid >> 1) * 32;
    const int wn3 = (wid & 1) * 32;
    float C3[2][4][4];
    #pragma unroll
    for (int i = 0; i < 2; i++)
        #pragma unroll
        for (int j = 0; j < 4; j++)
            #pragma unroll
            for (int q = 0; q < 4; q++) C3[i][j][q] = 0.f;
    #pragma unroll
    for (int c = 0; c < 2; c++)
        mma_chunk<4>(C3, uAh[c], uAl[c], uBh[c], uBl[c], wm3, wn3, lane);

    // epilogue 3: tanhshrink -> fp32 a3 in T region [128][68]
    {
        float* a3 = (float*)(sm + OFF_T);
        const int r0 = wm3 + (lane >> 2);
        const int c0 = wn3 + (lane & 3) * 2;
        #pragma unroll
        for (int mt = 0; mt < 2; mt++) {
            #pragma unroll
            for (int nt = 0; nt < 4; nt++) {
                const int n = c0 + nt * 8;
                const float b0v = sb3[n], b1v = sb3[n + 1];
                float v;
                v = C3[mt][nt][0] + b0v; a3[(r0 + mt * 16) * 68 + n]     = v - tanhf(v);
                v = C3[mt][nt][1] + b1v; a3[(r0 + mt * 16) * 68 + n + 1] = v - tanhf(v);
                v = C3[mt][nt][2] + b0v; a3[(r0 + mt * 16 + 8) * 68 + n]     = v - tanhf(v);
                v = C3[mt][nt][3] + b1v; a3[(r0 + mt * 16 + 8) * 68 + n + 1] = v - tanhf(v);
            }
        }
    }
    __syncthreads();

    // -------- layer 4 + sigmoid --------
    {
        const float* a3 = (const float*)(sm + OFF_T);
        const int row = tid >> 1;
        const int c = tid & 1;
        float s = sb4[c];
        #pragma unroll
        for (int k = 0; k < 64; k++) s += a3[row * 68 + k] * sW4[k * 2 + c];
        out[(size_t)(b0 + row) * 2 + c] = 1.f / (1.f + expf(-s));
    }
}

// ---------------- launch ----------------
extern "C" void kernel_launch(void* const* d_in, const int* in_sizes, int n_in,
                              void* d_out, int out_size) {
    const float* x    = (const float*)d_in[0];
    const int*   apps = (const int*)d_in[1];
    const int*   es   = (const int*)d_in[2];
    const int*   ed   = (const int*)d_in[3];
    const float* emb  = (const float*)d_in[4];
    const float* gcw  = (const float*)d_in[5];
    const float* gcb  = (const float*)d_in[6];
    const float* W1   = (const float*)d_in[7];
    const float* b1   = (const float*)d_in[8];
    const float* W2   = (const float*)d_in[9];
    const float* b2   = (const float*)d_in[10];
    const float* W3   = (const float*)d_in[11];
    const float* b3   = (const float*)d_in[12];
    const float* W4   = (const float*)d_in[13];
    const float* b4   = (const float*)d_in[14];
    float* out = (float*)d_out;

    cudaFuncSetAttribute(mlp_kernel, cudaFuncAttributeMaxDynamicSharedMemorySize, SMEM_BYTES);

    prep_graph<<<1, 256>>>(es, ed, emb, gcw, gcb);
    prep_weights<<<512, 256>>>(W1, W2, W3);
    gconv_kernel<<<B_TOTAL / GC_ROWS, 256>>>(apps);
    mlp_kernel<<<B_TOTAL / BM, 256, SMEM_BYTES>>>(x, b1, b2, b3, b4, W4, out);
}

// round 4
// speedup vs baseline: 2.5778x; 1.4045x over previous
#include <cuda_runtime.h>
#include <cuda_bf16.h>
#include <cstdint>

#define B_TOTAL 16384
#define NNODES  200
#define NEDGES  800
#define XF      2600
#define FEATR   2800
#define FEATP   2816          // K padded to 44*64
#define BM      64
#define NT1     (FEATP / 64)  // 44

// ---------------- device scratch ----------------
__device__ __align__(16) float g_gbuf[(size_t)B_TOTAL * NNODES];
__device__ float g_norm_dst[NNODES];
__device__ float g_ew[3];
__device__ float g_gcb;
__device__ int   g_csr_off[NNODES + 1];
__device__ int   g_csr_src[NEDGES];
__device__ float g_csr_w[NEDGES];
__device__ __align__(16) __nv_bfloat16 g_w1t_hi[128 * FEATP];
__device__ __align__(16) __nv_bfloat16 g_w1t_lo[128 * FEATP];
__device__ __align__(16) __nv_bfloat16 g_w2t_hi[128 * 128];
__device__ __align__(16) __nv_bfloat16 g_w2t_lo[128 * 128];
__device__ __align__(16) __nv_bfloat16 g_w3t_hi[64 * 128];
__device__ __align__(16) __nv_bfloat16 g_w3t_lo[64 * 128];

// ---------------- helpers ----------------
__device__ __forceinline__ uint32_t smem_to_u32(const void* p) {
    uint32_t a;
    asm("{ .reg .u64 t; cvta.to.shared.u64 t, %1; cvt.u32.u64 %0, t; }" : "=r"(a) : "l"(p));
    return a;
}
#define SWZ(off) ((off) ^ (((off) >> 3) & 0x70))

__device__ __forceinline__ void ldsm4(uint32_t r[4], uint32_t addr) {
    asm volatile("ldmatrix.sync.aligned.m8n8.x4.shared.b16 {%0,%1,%2,%3}, [%4];"
                 : "=r"(r[0]), "=r"(r[1]), "=r"(r[2]), "=r"(r[3]) : "r"(addr));
}
__device__ __forceinline__ void mma16816(float c[4], const uint32_t a[4],
                                         uint32_t b0, uint32_t b1) {
    asm volatile("mma.sync.aligned.m16n8k16.row.col.f32.bf16.bf16.f32 "
                 "{%0,%1,%2,%3}, {%4,%5,%6,%7}, {%8,%9}, {%0,%1,%2,%3};"
                 : "+f"(c[0]), "+f"(c[1]), "+f"(c[2]), "+f"(c[3])
                 : "r"(a[0]), "r"(a[1]), "r"(a[2]), "r"(a[3]), "r"(b0), "r"(b1));
}
__device__ __forceinline__ void cpa16(uint32_t dst, const void* src) {
    asm volatile("cp.async.cg.shared.global [%0], [%1], 16;" :: "r"(dst), "l"(src));
}
#define CPA_COMMIT() asm volatile("cp.async.commit_group;" ::: "memory")
#define CPA_WAIT0()  asm volatile("cp.async.wait_group 0;" ::: "memory")

__device__ __forceinline__ uint32_t pack_bf16x2(float even, float odd) {
    uint32_t r;
    asm("cvt.rn.bf16x2.f32 %0, %1, %2;" : "=r"(r) : "f"(odd), "f"(even));
    return r;
}
__device__ __forceinline__ void split2(float a, float b, uint32_t& hi2, uint32_t& lo2) {
    hi2 = pack_bf16x2(a, b);
    float ah = __uint_as_float(hi2 << 16);
    float bh = __uint_as_float(hi2 & 0xFFFF0000u);
    lo2 = pack_bf16x2(a - ah, b - bh);
}
__device__ __forceinline__ float softplusf(float x) {
    return fmaxf(x, 0.f) + log1pf(expf(-fabsf(x)));
}

// ---------------- smem layout (bytes) ----------------
#define OFF_B1   0          // 128 f
#define OFF_B2   512
#define OFF_B3   1024       // 64 f
#define OFF_B4   1280       // 2 f
#define OFF_W4   1536       // 128 f
#define OFF_A    2048       // A: hi[2] @ +0,+8K ; lo[2] @ +16K,+24K  (4 x 8KB)
#define OFF_BW   34816      // B: hi[2] @ +0,+16K ; lo[2] @ +32K,+48K (4 x 16KB)
#define SMEM_BYTES 100352

// ---------------- prep kernels ----------------
__global__ void prep_graph(const int* __restrict__ es, const int* __restrict__ ed,
                           const float* __restrict__ emb, const float* __restrict__ gcw,
                           const float* __restrict__ gcb) {
    __shared__ int cnto[NNODES], cnti[NNODES], pos[NNODES];
    int tid = threadIdx.x;
    for (int n = tid; n < NNODES; n += 256) { cnto[n] = 0; cnti[n] = 0; }
    __syncthreads();
    for (int e = tid; e < NEDGES; e += 256) {
        atomicAdd(&cnto[es[e]], 1);
        atomicAdd(&cnti[ed[e]], 1);
    }
    __syncthreads();
    for (int n = tid; n < NNODES; n += 256)
        g_norm_dst[n] = rsqrtf((float)max(cnti[n], 1));
    if (tid < 3) {
        float s = 0.f;
        #pragma unroll
        for (int j = 0; j < 5; j++) s += emb[tid * 5 + j] * gcw[j];
        g_ew[tid] = s;
    }
    if (tid == 0) {
        g_gcb = gcb[0];
        int off = 0;
        for (int d = 0; d < NNODES; d++) { g_csr_off[d] = off; pos[d] = off; off += cnti[d]; }
        g_csr_off[NNODES] = off;
    }
    __syncthreads();
    for (int e = tid; e < NEDGES; e += 256) {
        int d = ed[e], s = es[e];
        int p = atomicAdd(&pos[d], 1);
        g_csr_src[p] = s;
        g_csr_w[p] = rsqrtf((float)max(cnto[s], 1));
    }
}

__global__ void prep_weights(const float* __restrict__ W1, const float* __restrict__ W2,
                             const float* __restrict__ W3) {
    const int T1 = 128 * FEATP, T2 = 128 * 128, T3 = 64 * 128;
    for (int i = blockIdx.x * blockDim.x + threadIdx.x; i < T1 + T2 + T3;
         i += gridDim.x * blockDim.x) {
        float v;
        __nv_bfloat16 *ph, *pl;
        if (i < T1) {
            int k = i % FEATP;
            int n = i / FEATP;
            v = (k < FEATR) ? W1[(size_t)k * 128 + n] : 0.f;
            ph = g_w1t_hi + i; pl = g_w1t_lo + i;
        } else if (i < T1 + T2) {
            int j = i - T1;
            int n = j >> 7, k = j & 127;
            v = W2[k * 128 + n];
            ph = g_w2t_hi + j; pl = g_w2t_lo + j;
        } else {
            int j = i - T1 - T2;
            int n = j >> 7, k = j & 127;
            v = W3[k * 64 + n];
            ph = g_w3t_hi + j; pl = g_w3t_lo + j;
        }
        __nv_bfloat16 h = __float2bfloat16(v);
        *ph = h;
        *pl = __float2bfloat16(v - __bfloat162float(h));
    }
}

#define GC_ROWS 8
__global__ __launch_bounds__(256) void gconv_kernel(const int* __restrict__ apps) {
    __shared__ float hw[GC_ROWS][NNODES];
    const int b0 = blockIdx.x * GC_ROWS;
    const int tid = threadIdx.x;
    for (int i = tid; i < GC_ROWS * NNODES; i += 256) {
        int r = i / NNODES, n = i % NNODES;
        hw[r][n] = g_ew[apps[(size_t)(b0 + r) * NNODES + n]];
    }
    __syncthreads();
    const float gcb = g_gcb;
    for (int i = tid; i < GC_ROWS * NNODES; i += 256) {
        int r = i / NNODES, d = i % NNODES;
        int o0 = g_csr_off[d], o1 = g_csr_off[d + 1];
        float s = 0.f;
        for (int e = o0; e < o1; e++) s += g_csr_w[e] * hw[r][g_csr_src[e]];
        g_gbuf[(size_t)(b0 + r) * NNODES + d] = g_norm_dst[d] * s + gcb;
    }
}

// ---------------- A loaders (regs <-> smem) ----------------
// Each thread owns row = tid>>2, 16 k-cols at kq0 = (tid&3)*16 (4 float4).
__device__ __forceinline__ void lda_regs(float4 (&pf)[4], const float* __restrict__ x,
                                         size_t xrow, size_t grow, int k0, int tid) {
    const int kq0 = (tid & 3) * 16;
    #pragma unroll
    for (int j = 0; j < 4; j++) {
        const int k = k0 + kq0 + j * 4;
        if (k + 3 < XF)       pf[j] = *(const float4*)(x + xrow + k);
        else if (k < FEATR)   pf[j] = *(const float4*)(g_gbuf + grow + (k - XF));
        else                  pf[j] = make_float4(0.f, 0.f, 0.f, 0.f);
    }
}
__device__ __forceinline__ void sta_regs(const float4 (&pf)[4], char* Ah, char* Al, int tid) {
    const int row = tid >> 2;
    const int kq0 = (tid & 3) * 16;
    #pragma unroll
    for (int j = 0; j < 4; j++) {
        const int kl = kq0 + j * 4;
        uint32_t h01, l01, h23, l23;
        split2(pf[j].x, pf[j].y, h01, l01);
        split2(pf[j].z, pf[j].w, h23, l23);
        const uint32_t off = SWZ((uint32_t)(row * 128 + kl * 2));
        *(uint2*)(Ah + off) = make_uint2(h01, h23);
        *(uint2*)(Al + off) = make_uint2(l01, l23);
    }
}

// B tile via cp.async: nrows x 64 k bf16, swizzled 128B rows
__device__ __forceinline__ void cpa_B_tile(const __nv_bfloat16* __restrict__ W, int ldk,
                                           int k0, uint32_t dst, int nrows, int tid) {
    const int nv = nrows * 8;
    for (int v = tid; v < nv; v += 256) {
        const int n = v >> 3, kq = (v & 7) * 8;
        cpa16(dst + SWZ((uint32_t)(n * 128 + kq * 2)), W + (size_t)n * ldk + k0 + kq);
    }
}

// ---------------- MMA chunk: warp tile 32 x (NTILES*8), K=64, split-bf16 ----------------
template<int NTILES>
__device__ __forceinline__ void mma_chunk(float (&C)[2][NTILES][4],
                                          uint32_t a_hi, uint32_t a_lo,
                                          uint32_t b_hi, uint32_t b_lo,
                                          int wm_base, int wn_base, int lane) {
    const int lr = (lane & 7) + ((lane >> 3) & 1) * 8;
    const int lh = (lane >> 4) * 16;
    #pragma unroll
    for (int kk = 0; kk < 4; kk++) {
        uint32_t ah[2][4], al[2][4];
        #pragma unroll
        for (int mt = 0; mt < 2; mt++) {
            uint32_t off = SWZ((uint32_t)((wm_base + mt * 16 + lr) * 128 + kk * 32 + lh));
            ldsm4(ah[mt], a_hi + off);
            ldsm4(al[mt], a_lo + off);
        }
        #pragma unroll
        for (int ng = 0; ng < NTILES / 2; ng++) {
            uint32_t off = SWZ((uint32_t)((wn_base + ng * 16 + lr) * 128 + kk * 32 + lh));
            uint32_t bh[4], bl[4];
            ldsm4(bh, b_hi + off);
            ldsm4(bl, b_lo + off);
            #pragma unroll
            for (int half = 0; half < 2; half++) {
                const int nt = ng * 2 + half;
                #pragma unroll
                for (int mt = 0; mt < 2; mt++) {
                    mma16816(C[mt][nt], ah[mt], bh[half], bh[half + 2]);
                    mma16816(C[mt][nt], ah[mt], bl[half], bl[half + 2]);
                    mma16816(C[mt][nt], al[mt], bh[half], bh[half + 2]);
                }
            }
        }
    }
}

// epilogue: bias + softplus, split-store to hi/lo chunked tiles in A region
__device__ __forceinline__ void epi_split(float (&C)[2][4][4], const float* bias,
                                          char* dhi, char* dlo,
                                          int wm_base, int wn_base, int lane) {
    const int r0 = wm_base + (lane >> 2);
    const int c0 = wn_base + (lane & 3) * 2;
    #pragma unroll
    for (int mt = 0; mt < 2; mt++) {
        #pragma unroll
        for (int nt = 0; nt < 4; nt++) {
            const int n = c0 + nt * 8;
            const int chunk = n >> 6, col = n & 63;
            const float b0 = bias[n], b1 = bias[n + 1];
            char* th = dhi + chunk * 8192;
            char* tl = dlo + chunk * 8192;
            {
                float v0 = softplusf(C[mt][nt][0] + b0);
                float v1 = softplusf(C[mt][nt][1] + b1);
                uint32_t h, l;
                split2(v0, v1, h, l);
                const uint32_t off = SWZ((uint32_t)((r0 + mt * 16) * 128 + col * 2));
                *(uint32_t*)(th + off) = h;
                *(uint32_t*)(tl + off) = l;
            }
            {
                float v0 = softplusf(C[mt][nt][2] + b0);
                float v1 = softplusf(C[mt][nt][3] + b1);
                uint32_t h, l;
                split2(v0, v1, h, l);
                const uint32_t off = SWZ((uint32_t)((r0 + mt * 16 + 8) * 128 + col * 2));
                *(uint32_t*)(th + off) = h;
                *(uint32_t*)(tl + off) = l;
            }
        }
    }
}

// ---------------- fused MLP kernel ----------------
__global__ __launch_bounds__(256, 2)
void mlp_kernel(const float* __restrict__ x,
                const float* __restrict__ b1g, const float* __restrict__ b2g,
                const float* __restrict__ b3g, const float* __restrict__ b4g,
                const float* __restrict__ W4g, float* __restrict__ out) {
    extern __shared__ char sm[];
    const uint32_t su = smem_to_u32(sm);
    const int tid = threadIdx.x;
    const int wid = tid >> 5;
    const int lane = tid & 31;
    const int b0 = blockIdx.x * BM;

    float* sb1 = (float*)(sm + OFF_B1);
    float* sb2 = (float*)(sm + OFF_B2);
    float* sb3 = (float*)(sm + OFF_B3);
    float* sb4 = (float*)(sm + OFF_B4);
    float* sW4 = (float*)(sm + OFF_W4);
    if (tid < 128) { sb1[tid] = b1g[tid]; sb2[tid] = b2g[tid]; sW4[tid] = W4g[tid]; }
    if (tid < 64) sb3[tid] = b3g[tid];
    if (tid < 2) sb4[tid] = b4g[tid];

    // A region: hi[b] @ +b*8K, lo[b] @ +16K+b*8K (also a1/a2 tiles, chunk=b)
    char* pAh[2] = { sm + OFF_A,          sm + OFF_A + 8192 };
    char* pAl[2] = { sm + OFF_A + 16384,  sm + OFF_A + 24576 };
    const uint32_t uAh[2] = { su + OFF_A,         su + OFF_A + 8192 };
    const uint32_t uAl[2] = { su + OFF_A + 16384, su + OFF_A + 24576 };
    // B region: 16KB tiles (W1/W2); W3 uses 8KB tiles
    const uint32_t uBh[2] = { su + OFF_BW,         su + OFF_BW + 16384 };
    const uint32_t uBl[2] = { su + OFF_BW + 32768, su + OFF_BW + 49152 };

    const size_t xrow = (size_t)(b0 + (tid >> 2)) * XF;
    const size_t grow = (size_t)(b0 + (tid >> 2)) * NNODES;

    const int wm = (wid >> 2) * 32;   // 2 M-groups of 32
    const int wn = (wid & 3) * 32;    // 4 N-groups of 32

    float C[2][4][4];
    #pragma unroll
    for (int i = 0; i < 2; i++)
        #pragma unroll
        for (int j = 0; j < 4; j++)
            #pragma unroll
            for (int q = 0; q < 4; q++) C[i][j][q] = 0.f;

    // -------- GEMM1: feat[64x2816] @ W1t -> C, software pipelined --------
    {
        float4 pf[4];
        lda_regs(pf, x, xrow, grow, 0, tid);
        sta_regs(pf, pAh[0], pAl[0], tid);
    }
    cpa_B_tile(g_w1t_hi, FEATP, 0, uBh[0], 128, tid);
    cpa_B_tile(g_w1t_lo, FEATP, 0, uBl[0], 128, tid);
    CPA_COMMIT();
    CPA_WAIT0();
    __syncthreads();

    for (int t = 0; t < NT1; t++) {
        const int cur = t & 1;
        const int nb = cur ^ 1;
        const bool more = (t + 1 < NT1);
        float4 pf[4];
        if (more) {
            const int k0 = (t + 1) * 64;
            cpa_B_tile(g_w1t_hi, FEATP, k0, uBh[nb], 128, tid);
            cpa_B_tile(g_w1t_lo, FEATP, k0, uBl[nb], 128, tid);
            CPA_COMMIT();
            lda_regs(pf, x, xrow, grow, k0, tid);   // LDG overlaps MMA below
        }
        mma_chunk<4>(C, uAh[cur], uAl[cur], uBh[cur], uBl[cur], wm, wn, lane);
        if (more) {
            sta_regs(pf, pAh[nb], pAl[nb], tid);
            CPA_WAIT0();
        }
        __syncthreads();
    }
    // epilogue 1: a1 = softplus(C + b1) -> A region tiles (hi/lo, 2 chunks)
    epi_split(C, sb1, sm + OFF_A, sm + OFF_A + 16384, wm, wn, lane);
    // W2 -> B region (B region free after final GEMM1 MMA + sync)
    cpa_B_tile(g_w2t_hi, 128, 0,  uBh[0], 128, tid);
    cpa_B_tile(g_w2t_hi, 128, 64, uBh[1], 128, tid);
    cpa_B_tile(g_w2t_lo, 128, 0,  uBl[0], 128, tid);
    cpa_B_tile(g_w2t_lo, 128, 64, uBl[1], 128, tid);
    CPA_COMMIT();
    CPA_WAIT0();
    __syncthreads();

    // -------- GEMM2: a1[64x128] @ W2t --------
    #pragma unroll
    for (int i = 0; i < 2; i++)
        #pragma unroll
        for (int j = 0; j < 4; j++)
            #pragma unroll
            for (int q = 0; q < 4; q++) C[i][j][q] = 0.f;
    #pragma unroll
    for (int c = 0; c < 2; c++)
        mma_chunk<4>(C, uAh[c], uAl[c], uBh[c], uBl[c], wm, wn, lane);
    __syncthreads();   // all warps done reading a1 before overwrite

    // epilogue 2: a2 -> A region (overwrites a1); W3 -> B region (8KB tiles)
    epi_split(C, sb2, sm + OFF_A, sm + OFF_A + 16384, wm, wn, lane);
    cpa_B_tile(g_w3t_hi, 128, 0,  su + OFF_BW,         64, tid);
    cpa_B_tile(g_w3t_hi, 128, 64, su + OFF_BW + 8192,  64, tid);
    cpa_B_tile(g_w3t_lo, 128, 0,  su + OFF_BW + 16384, 64, tid);
    cpa_B_tile(g_w3t_lo, 128, 64, su + OFF_BW + 24576, 64, tid);
    CPA_COMMIT();
    CPA_WAIT0();
    __syncthreads();

    // -------- GEMM3: a2[64x128] @ W3t (N=64), warp tile 32x16 --------
    const int wm3 = (wid >> 2) * 32;
    const int wn3 = (wid & 3) * 16;
    float C3[2][2][4];
    #pragma unroll
    for (int i = 0; i < 2; i++)
        #pragma unroll
        for (int j = 0; j < 2; j++)
            #pragma unroll
            for (int q = 0; q < 4; q++) C3[i][j][q] = 0.f;
    #pragma unroll
    for (int c = 0; c < 2; c++)
        mma_chunk<2>(C3, uAh[c], uAl[c],
                     su + OFF_BW + c * 8192, su + OFF_BW + 16384 + c * 8192,
                     wm3, wn3, lane);
    __syncthreads();   // done reading a2

    // epilogue 3: tanhshrink -> fp32 a3[64][68] in A region
    {
        float* a3 = (float*)(sm + OFF_A);
        const int r0 = wm3 + (lane >> 2);
        const int c0 = wn3 + (lane & 3) * 2;
        #pragma unroll
        for (int mt = 0; mt < 2; mt++) {
            #pragma unroll
            for (int nt = 0; nt < 2; nt++) {
                const int n = c0 + nt * 8;
                const float b0v = sb3[n], b1v = sb3[n + 1];
                float v;
                v = C3[mt][nt][0] + b0v; a3[(r0 + mt * 16) * 68 + n]     = v - tanhf(v);
                v = C3[mt][nt][1] + b1v; a3[(r0 + mt * 16) * 68 + n + 1] = v - tanhf(v);
                v = C3[mt][nt][2] + b0v; a3[(r0 + mt * 16 + 8) * 68 + n]     = v - tanhf(v);
                v = C3[mt][nt][3] + b1v; a3[(r0 + mt * 16 + 8) * 68 + n + 1] = v - tanhf(v);
            }
        }
    }
    __syncthreads();

    // -------- layer 4 + sigmoid (64 rows x 2 outputs -> 128 threads) --------
    if (tid < 128) {
        const float* a3 = (const float*)(sm + OFF_A);
        const int row = tid >> 1;
        const int c = tid & 1;
        float s = sb4[c];
        #pragma unroll
        for (int k = 0; k < 64; k++) s += a3[row * 68 + k] * sW4[k * 2 + c];
        out[(size_t)(b0 + row) * 2 + c] = 1.f / (1.f + expf(-s));
    }
}

// ---------------- launch ----------------
extern "C" void kernel_launch(void* const* d_in, const int* in_sizes, int n_in,
                              void* d_out, int out_size) {
    const float* x    = (const float*)d_in[0];
    const int*   apps = (const int*)d_in[1];
    const int*   es   = (const int*)d_in[2];
    const int*   ed   = (const int*)d_in[3];
    const float* emb  = (const float*)d_in[4];
    const float* gcw  = (const float*)d_in[5];
    const float* gcb  = (const float*)d_in[6];
    const float* W1   = (const float*)d_in[7];
    const float* b1   = (const float*)d_in[8];
    const float* W2   = (const float*)d_in[9];
    const float* b2   = (const float*)d_in[10];
    const float* W3   = (const float*)d_in[11];
    const float* b3   = (const float*)d_in[12];
    const float* W4   = (const float*)d_in[13];
    const float* b4   = (const float*)d_in[14];
    float* out = (float*)d_out;

    cudaFuncSetAttribute(mlp_kernel, cudaFuncAttributeMaxDynamicSharedMemorySize, SMEM_BYTES);

    prep_graph<<<1, 256>>>(es, ed, emb, gcw, gcb);
    prep_weights<<<512, 256>>>(W1, W2, W3);
    gconv_kernel<<<B_TOTAL / GC_ROWS, 256>>>(apps);
    mlp_kernel<<<B_TOTAL / BM, 256, SMEM_BYTES>>>(x, b1, b2, b3, b4, W4, out);
}

// round 5
// speedup vs baseline: 2.7519x; 1.0676x over previous
#include <cuda_runtime.h>
#include <cuda_bf16.h>
#include <cstdint>

#define B_TOTAL 16384
#define NNODES  200
#define NEDGES  800
#define XF      2600
#define FEATR   2800
#define FEATP   2816          // K padded to 44*64
#define NT1     (FEATP / 64)  // 44

// ---------------- device scratch ----------------
__device__ __align__(16) float g_gbuf[(size_t)B_TOTAL * NNODES];
__device__ __align__(16) float g_a1[(size_t)B_TOTAL * 128];
__device__ float g_norm_dst[NNODES];
__device__ float g_ew[3];
__device__ float g_gcb;
__device__ int   g_csr_off[NNODES + 1];
__device__ int   g_csr_src[NEDGES];
__device__ float g_csr_w[NEDGES];
__device__ __align__(16) __nv_bfloat16 g_w1t_hi[128 * FEATP];
__device__ __align__(16) __nv_bfloat16 g_w1t_lo[128 * FEATP];
__device__ __align__(16) __nv_bfloat16 g_w2t_hi[128 * 128];
__device__ __align__(16) __nv_bfloat16 g_w2t_lo[128 * 128];
__device__ __align__(16) __nv_bfloat16 g_w3t_hi[64 * 128];
__device__ __align__(16) __nv_bfloat16 g_w3t_lo[64 * 128];

// ---------------- helpers ----------------
__device__ __forceinline__ uint32_t smem_to_u32(const void* p) {
    uint32_t a;
    asm("{ .reg .u64 t; cvta.to.shared.u64 t, %1; cvt.u32.u64 %0, t; }" : "=r"(a) : "l"(p));
    return a;
}
#define SWZ(off) ((off) ^ (((off) >> 3) & 0x70))

__device__ __forceinline__ void ldsm4(uint32_t r[4], uint32_t addr) {
    asm volatile("ldmatrix.sync.aligned.m8n8.x4.shared.b16 {%0,%1,%2,%3}, [%4];"
                 : "=r"(r[0]), "=r"(r[1]), "=r"(r[2]), "=r"(r[3]) : "r"(addr));
}
__device__ __forceinline__ void mma16816(float c[4], const uint32_t a[4],
                                         uint32_t b0, uint32_t b1) {
    asm volatile("mma.sync.aligned.m16n8k16.row.col.f32.bf16.bf16.f32 "
                 "{%0,%1,%2,%3}, {%4,%5,%6,%7}, {%8,%9}, {%0,%1,%2,%3};"
                 : "+f"(c[0]), "+f"(c[1]), "+f"(c[2]), "+f"(c[3])
                 : "r"(a[0]), "r"(a[1]), "r"(a[2]), "r"(a[3]), "r"(b0), "r"(b1));
}
__device__ __forceinline__ void cpa16(uint32_t dst, const void* src) {
    asm volatile("cp.async.cg.shared.global [%0], [%1], 16;" :: "r"(dst), "l"(src));
}
#define CPA_COMMIT() asm volatile("cp.async.commit_group;" ::: "memory")
#define CPA_WAIT0()  asm volatile("cp.async.wait_group 0;" ::: "memory")

__device__ __forceinline__ uint32_t pack_bf16x2(float even, float odd) {
    uint32_t r;
    asm("cvt.rn.bf16x2.f32 %0, %1, %2;" : "=r"(r) : "f"(odd), "f"(even));
    return r;
}
__device__ __forceinline__ void split2(float a, float b, uint32_t& hi2, uint32_t& lo2) {
    hi2 = pack_bf16x2(a, b);
    float ah = __uint_as_float(hi2 << 16);
    float bh = __uint_as_float(hi2 & 0xFFFF0000u);
    lo2 = pack_bf16x2(a - ah, b - bh);
}
__device__ __forceinline__ float softplusf(float x) {
    return fmaxf(x, 0.f) + log1pf(expf(-fabsf(x)));
}

// ---------------- MMA chunk: warp tile (2*16) x (NTILES*8), K=64 ----------------
template<int NTILES>
__device__ __forceinline__ void mma_chunk(float (&C)[2][NTILES][4],
                                          uint32_t a_hi, uint32_t a_lo,
                                          uint32_t b_hi, uint32_t b_lo,
                                          int wm_base, int wn_base, int lane) {
    const int lr = (lane & 7) + ((lane >> 3) & 1) * 8;
    const int lh = (lane >> 4) * 16;
    #pragma unroll
    for (int kk = 0; kk < 4; kk++) {
        uint32_t ah[2][4], al[2][4];
        #pragma unroll
        for (int mt = 0; mt < 2; mt++) {
            uint32_t off = SWZ((uint32_t)((wm_base + mt * 16 + lr) * 128 + kk * 32 + lh));
            ldsm4(ah[mt], a_hi + off);
            ldsm4(al[mt], a_lo + off);
        }
        #pragma unroll
        for (int ng = 0; ng < NTILES / 2; ng++) {
            uint32_t off = SWZ((uint32_t)((wn_base + ng * 16 + lr) * 128 + kk * 32 + lh));
            uint32_t bh[4], bl[4];
            ldsm4(bh, b_hi + off);
            ldsm4(bl, b_lo + off);
            #pragma unroll
            for (int half = 0; half < 2; half++) {
                const int nt = ng * 2 + half;
                #pragma unroll
                for (int mt = 0; mt < 2; mt++) {
                    mma16816(C[mt][nt], ah[mt], bh[half], bh[half + 2]);
                    mma16816(C[mt][nt], ah[mt], bl[half], bl[half + 2]);
                    mma16816(C[mt][nt], al[mt], bh[half], bh[half + 2]);
                }
            }
        }
    }
}

// ---------------- prep: graph (block 0) + weight transpose/split (all) ----------------
__global__ void prep_kernel(const int* __restrict__ es, const int* __restrict__ ed,
                            const float* __restrict__ emb, const float* __restrict__ gcw,
                            const float* __restrict__ gcb,
                            const float* __restrict__ W1, const float* __restrict__ W2,
                            const float* __restrict__ W3) {
    const int tid = threadIdx.x;
    if (blockIdx.x == 0) {
        __shared__ int cnto[NNODES], cnti[NNODES], pos[NNODES];
        for (int n = tid; n < NNODES; n += 256) { cnto[n] = 0; cnti[n] = 0; }
        __syncthreads();
        for (int e = tid; e < NEDGES; e += 256) {
            atomicAdd(&cnto[es[e]], 1);
            atomicAdd(&cnti[ed[e]], 1);
        }
        __syncthreads();
        for (int n = tid; n < NNODES; n += 256)
            g_norm_dst[n] = rsqrtf((float)max(cnti[n], 1));
        if (tid < 3) {
            float s = 0.f;
            #pragma unroll
            for (int j = 0; j < 5; j++) s += emb[tid * 5 + j] * gcw[j];
            g_ew[tid] = s;
        }
        if (tid == 0) {
            g_gcb = gcb[0];
            int off = 0;
            for (int d = 0; d < NNODES; d++) { g_csr_off[d] = off; pos[d] = off; off += cnti[d]; }
            g_csr_off[NNODES] = off;
        }
        __syncthreads();
        for (int e = tid; e < NEDGES; e += 256) {
            int d = ed[e], s = es[e];
            int p = atomicAdd(&pos[d], 1);
            g_csr_src[p] = s;
            g_csr_w[p] = rsqrtf((float)max(cnto[s], 1));
        }
    }
    // weights (all blocks, grid-stride)
    const int T1 = 128 * FEATP, T2 = 128 * 128, T3 = 64 * 128;
    for (int i = blockIdx.x * blockDim.x + tid; i < T1 + T2 + T3;
         i += gridDim.x * blockDim.x) {
        float v;
        __nv_bfloat16 *ph, *pl;
        if (i < T1) {
            int k = i % FEATP;
            int n = i / FEATP;
            v = (k < FEATR) ? W1[(size_t)k * 128 + n] : 0.f;
            ph = g_w1t_hi + i; pl = g_w1t_lo + i;
        } else if (i < T1 + T2) {
            int j = i - T1;
            int n = j >> 7, k = j & 127;
            v = W2[k * 128 + n];
            ph = g_w2t_hi + j; pl = g_w2t_lo + j;
        } else {
            int j = i - T1 - T2;
            int n = j >> 7, k = j & 127;
            v = W3[k * 64 + n];
            ph = g_w3t_hi + j; pl = g_w3t_lo + j;
        }
        __nv_bfloat16 h = __float2bfloat16(v);
        *ph = h;
        *pl = __float2bfloat16(v - __bfloat162float(h));
    }
}

#define GC_ROWS 8
__global__ __launch_bounds__(256) void gconv_kernel(const int* __restrict__ apps) {
    __shared__ float hw[GC_ROWS][NNODES];
    const int b0 = blockIdx.x * GC_ROWS;
    const int tid = threadIdx.x;
    for (int i = tid; i < GC_ROWS * NNODES; i += 256) {
        int r = i / NNODES, n = i % NNODES;
        hw[r][n] = g_ew[apps[(size_t)(b0 + r) * NNODES + n]];
    }
    __syncthreads();
    const float gcb = g_gcb;
    for (int i = tid; i < GC_ROWS * NNODES; i += 256) {
        int r = i / NNODES, d = i % NNODES;
        int o0 = g_csr_off[d], o1 = g_csr_off[d + 1];
        float s = 0.f;
        for (int e = o0; e < o1; e++) s += g_csr_w[e] * hw[r][g_csr_src[e]];
        g_gbuf[(size_t)(b0 + r) * NNODES + d] = g_norm_dst[d] * s + gcb;
    }
}

// ================= GEMM1 kernel: a1 = softplus(feat @ W1 + b1) =================
// BM=128, N=128, 512 threads, 1 CTA/SM, grid 128.
#define G1_OFF_B1 0
#define G1_OFF_A  1024                   // hi[2] @ +0,+16K ; lo[2] @ +32K,+48K
#define G1_OFF_BW (1024 + 65536)         // hi[2] @ +0,+16K ; lo[2] @ +32K,+48K
#define G1_SMEM   (1024 + 65536 + 65536)

__device__ __forceinline__ void g1_lda(float4 (&pf)[4], const float* __restrict__ xr,
                                       const float* __restrict__ gr, int k0, int kq0) {
    if (k0 + 63 < XF) {
        #pragma unroll
        for (int j = 0; j < 4; j++) pf[j] = *(const float4*)(xr + k0 + kq0 + j * 4);
    } else {
        #pragma unroll
        for (int j = 0; j < 4; j++) {
            const int k = k0 + kq0 + j * 4;
            if (k + 3 < XF)       pf[j] = *(const float4*)(xr + k);
            else if (k < FEATR)   pf[j] = *(const float4*)(gr + (k - XF));
            else                  pf[j] = make_float4(0.f, 0.f, 0.f, 0.f);
        }
    }
}
__device__ __forceinline__ void g1_sta(const float4 (&pf)[4], char* Ah, char* Al,
                                       int row, int kq0) {
    #pragma unroll
    for (int j = 0; j < 4; j++) {
        const int kl = kq0 + j * 4;
        uint32_t h01, l01, h23, l23;
        split2(pf[j].x, pf[j].y, h01, l01);
        split2(pf[j].z, pf[j].w, h23, l23);
        const uint32_t off = SWZ((uint32_t)(row * 128 + kl * 2));
        *(uint2*)(Ah + off) = make_uint2(h01, h23);
        *(uint2*)(Al + off) = make_uint2(l01, l23);
    }
}

__global__ __launch_bounds__(512, 1)
void gemm1_kernel(const float* __restrict__ x, const float* __restrict__ b1g) {
    extern __shared__ char sm[];
    const uint32_t su = smem_to_u32(sm);
    const int tid = threadIdx.x;
    const int wid = tid >> 5;
    const int lane = tid & 31;
    const int b0 = blockIdx.x * 128;

    float* sb1 = (float*)(sm + G1_OFF_B1);
    if (tid < 128) sb1[tid] = b1g[tid];

    char* pAh[2] = { sm + G1_OFF_A,          sm + G1_OFF_A + 16384 };
    char* pAl[2] = { sm + G1_OFF_A + 32768,  sm + G1_OFF_A + 49152 };
    const uint32_t uAh[2] = { su + G1_OFF_A,         su + G1_OFF_A + 16384 };
    const uint32_t uAl[2] = { su + G1_OFF_A + 32768, su + G1_OFF_A + 49152 };
    const uint32_t uBh[2] = { su + G1_OFF_BW,         su + G1_OFF_BW + 16384 };
    const uint32_t uBl[2] = { su + G1_OFF_BW + 32768, su + G1_OFF_BW + 49152 };

    // A loader: row = tid>>2 (0..127), kq0 = (tid&3)*16
    const int arow = tid >> 2;
    const int kq0  = (tid & 3) * 16;
    const float* xr = x + (size_t)(b0 + arow) * XF;
    const float* gr = g_gbuf + (size_t)(b0 + arow) * NNODES;

    // B loader: 2 vectors per level per thread; precompute smem swz offsets + gmem ptrs
    const int bv0 = tid, bv1 = tid + 512;
    const uint32_t bs0 = SWZ((uint32_t)((bv0 >> 3) * 128 + (bv0 & 7) * 16));
    const uint32_t bs1 = SWZ((uint32_t)((bv1 >> 3) * 128 + (bv1 & 7) * 16));
    const __nv_bfloat16* gh0 = g_w1t_hi + (size_t)(bv0 >> 3) * FEATP + (bv0 & 7) * 8;
    const __nv_bfloat16* gh1 = g_w1t_hi + (size_t)(bv1 >> 3) * FEATP + (bv1 & 7) * 8;
    const __nv_bfloat16* gl0 = g_w1t_lo + (size_t)(bv0 >> 3) * FEATP + (bv0 & 7) * 8;
    const __nv_bfloat16* gl1 = g_w1t_lo + (size_t)(bv1 >> 3) * FEATP + (bv1 & 7) * 8;

    const int wm = (wid >> 2) * 32;
    const int wn = (wid & 3) * 32;

    float C[2][4][4];
    #pragma unroll
    for (int i = 0; i < 2; i++)
        #pragma unroll
        for (int j = 0; j < 4; j++)
            #pragma unroll
            for (int q = 0; q < 4; q++) C[i][j][q] = 0.f;

    // prologue: buffer 0
    {
        float4 pf[4];
        g1_lda(pf, xr, gr, 0, kq0);
        g1_sta(pf, pAh[0], pAl[0], arow, kq0);
        cpa16(uBh[0] + bs0, gh0);
        cpa16(uBh[0] + bs1, gh1);
        cpa16(uBl[0] + bs0, gl0);
        cpa16(uBl[0] + bs1, gl1);
        CPA_COMMIT();
        CPA_WAIT0();
    }
    __syncthreads();

    for (int t = 0; t < NT1; t++) {
        const int cur = t & 1;
        const int nb = cur ^ 1;
        const bool more = (t + 1 < NT1);
        float4 pf[4];
        if (more) {
            const int koff = (t + 1) * 64;
            cpa16(uBh[nb] + bs0, gh0 + koff);
            cpa16(uBh[nb] + bs1, gh1 + koff);
            cpa16(uBl[nb] + bs0, gl0 + koff);
            cpa16(uBl[nb] + bs1, gl1 + koff);
            CPA_COMMIT();
            g1_lda(pf, xr, gr, koff, kq0);
        }
        mma_chunk<4>(C, uAh[cur], uAl[cur], uBh[cur], uBl[cur], wm, wn, lane);
        if (more) {
            g1_sta(pf, pAh[nb], pAl[nb], arow, kq0);
            CPA_WAIT0();
        }
        __syncthreads();
    }

    // epilogue: bias + softplus -> g_a1 (f32)
    {
        const int r0 = wm + (lane >> 2);
        const int c0 = wn + (lane & 3) * 2;
        #pragma unroll
        for (int mt = 0; mt < 2; mt++) {
            #pragma unroll
            for (int nt = 0; nt < 4; nt++) {
                const int c = c0 + nt * 8;
                const float bb0 = sb1[c], bb1 = sb1[c + 1];
                float2 v01 = make_float2(softplusf(C[mt][nt][0] + bb0),
                                         softplusf(C[mt][nt][1] + bb1));
                float2 v23 = make_float2(softplusf(C[mt][nt][2] + bb0),
                                         softplusf(C[mt][nt][3] + bb1));
                *(float2*)(g_a1 + (size_t)(b0 + r0 + mt * 16) * 128 + c) = v01;
                *(float2*)(g_a1 + (size_t)(b0 + r0 + mt * 16 + 8) * 128 + c) = v23;
            }
        }
    }
}

// ================= kernel 2: layers 2-4 =================
// BM=64, 256 threads, 2 CTAs/SM, grid 256.
#define M2_OFF_B2 0
#define M2_OFF_B3 512
#define M2_OFF_B4 768
#define M2_OFF_W4 1024
#define M2_OFF_A  2048                    // a tiles: hi[2] @ +0,+8K ; lo[2] @ +16K,+24K (32KB)
#define M2_OFF_BW (2048 + 32768)          // W tiles: hi[2] @ +0,+16K ; lo[2] @ +32K,+48K (64KB)
#define M2_SMEM   (2048 + 32768 + 65536)

__device__ __forceinline__ void m2_cpa_W(const __nv_bfloat16* __restrict__ W, int ldk,
                                         int k0, uint32_t dst, int nrows, int tid) {
    const int nv = nrows * 8;
    for (int v = tid; v < nv; v += 256) {
        const int n = v >> 3, kq = (v & 7) * 8;
        cpa16(dst + SWZ((uint32_t)(n * 128 + kq * 2)), W + (size_t)n * ldk + k0 + kq);
    }
}

__device__ __forceinline__ void m2_epi_split(float (&C)[2][4][4], const float* bias,
                                             char* dhi, char* dlo,
                                             int wm_base, int wn_base, int lane) {
    const int r0 = wm_base + (lane >> 2);
    const int c0 = wn_base + (lane & 3) * 2;
    #pragma unroll
    for (int mt = 0; mt < 2; mt++) {
        #pragma unroll
        for (int nt = 0; nt < 4; nt++) {
            const int n = c0 + nt * 8;
            const int chunk = n >> 6, col = n & 63;
            const float b0 = bias[n], b1 = bias[n + 1];
            char* th = dhi + chunk * 8192;
            char* tl = dlo + chunk * 8192;
            {
                float v0 = softplusf(C[mt][nt][0] + b0);
                float v1 = softplusf(C[mt][nt][1] + b1);
                uint32_t h, l;
                split2(v0, v1, h, l);
                const uint32_t off = SWZ((uint32_t)((r0 + mt * 16) * 128 + col * 2));
                *(uint32_t*)(th + off) = h;
                *(uint32_t*)(tl + off) = l;
            }
            {
                float v0 = softplusf(C[mt][nt][2] + b0);
                float v1 = softplusf(C[mt][nt][3] + b1);
                uint32_t h, l;
                split2(v0, v1, h, l);
                const uint32_t off = SWZ((uint32_t)((r0 + mt * 16 + 8) * 128 + col * 2));
                *(uint32_t*)(th + off) = h;
                *(uint32_t*)(tl + off) = l;
            }
        }
    }
}

__global__ __launch_bounds__(256, 2)
void mlp2_kernel(const float* __restrict__ b2g, const float* __restrict__ b3g,
                 const float* __restrict__ b4g, const float* __restrict__ W4g,
                 float* __restrict__ out) {
    extern __shared__ char sm[];
    const uint32_t su = smem_to_u32(sm);
    const int tid = threadIdx.x;
    const int wid = tid >> 5;
    const int lane = tid & 31;
    const int b0 = blockIdx.x * 64;

    float* sb2 = (float*)(sm + M2_OFF_B2);
    float* sb3 = (float*)(sm + M2_OFF_B3);
    float* sb4 = (float*)(sm + M2_OFF_B4);
    float* sW4 = (float*)(sm + M2_OFF_W4);
    if (tid < 128) { sb2[tid] = b2g[tid]; sW4[tid] = W4g[tid]; }
    if (tid < 64) sb3[tid] = b3g[tid];
    if (tid < 2) sb4[tid] = b4g[tid];

    char* pAh[2] = { sm + M2_OFF_A,          sm + M2_OFF_A + 8192 };
    char* pAl[2] = { sm + M2_OFF_A + 16384,  sm + M2_OFF_A + 24576 };
    const uint32_t uAh[2] = { su + M2_OFF_A,         su + M2_OFF_A + 8192 };
    const uint32_t uAl[2] = { su + M2_OFF_A + 16384, su + M2_OFF_A + 24576 };
    const uint32_t uBh[2] = { su + M2_OFF_BW,         su + M2_OFF_BW + 16384 };
    const uint32_t uBl[2] = { su + M2_OFF_BW + 32768, su + M2_OFF_BW + 49152 };

    // W2 tiles early
    m2_cpa_W(g_w2t_hi, 128, 0,  uBh[0], 128, tid);
    m2_cpa_W(g_w2t_hi, 128, 64, uBh[1], 128, tid);
    m2_cpa_W(g_w2t_lo, 128, 0,  uBl[0], 128, tid);
    m2_cpa_W(g_w2t_lo, 128, 64, uBl[1], 128, tid);
    CPA_COMMIT();

    // load a1 (f32) + split into A tiles
    {
        const int row = tid >> 2;
        const int kq0 = (tid & 3) * 16;
        const float* ar = g_a1 + (size_t)(b0 + row) * 128;
        #pragma unroll
        for (int c = 0; c < 2; c++) {
            #pragma unroll
            for (int j = 0; j < 4; j++) {
                const int kl = kq0 + j * 4;
                float4 f = *(const float4*)(ar + c * 64 + kl);
                uint32_t h01, l01, h23, l23;
                split2(f.x, f.y, h01, l01);
                split2(f.z, f.w, h23, l23);
                const uint32_t off = SWZ((uint32_t)(row * 128 + kl * 2));
                *(uint2*)(pAh[c] + off) = make_uint2(h01, h23);
                *(uint2*)(pAl[c] + off) = make_uint2(l01, l23);
            }
        }
    }
    CPA_WAIT0();
    __syncthreads();

    const int wm = (wid >> 2) * 32;
    const int wn = (wid & 3) * 32;

    // GEMM2
    float C[2][4][4];
    #pragma unroll
    for (int i = 0; i < 2; i++)
        #pragma unroll
        for (int j = 0; j < 4; j++)
            #pragma unroll
            for (int q = 0; q < 4; q++) C[i][j][q] = 0.f;
    #pragma unroll
    for (int c = 0; c < 2; c++)
        mma_chunk<4>(C, uAh[c], uAl[c], uBh[c], uBl[c], wm, wn, lane);
    __syncthreads();

    // epi2 -> a2 tiles (overwrite a1); W3 tiles -> B region (8KB each)
    m2_epi_split(C, sb2, sm + M2_OFF_A, sm + M2_OFF_A + 16384, wm, wn, lane);
    m2_cpa_W(g_w3t_hi, 128, 0,  su + M2_OFF_BW,         64, tid);
    m2_cpa_W(g_w3t_hi, 128, 64, su + M2_OFF_BW + 8192,  64, tid);
    m2_cpa_W(g_w3t_lo, 128, 0,  su + M2_OFF_BW + 16384, 64, tid);
    m2_cpa_W(g_w3t_lo, 128, 64, su + M2_OFF_BW + 24576, 64, tid);
    CPA_COMMIT();
    CPA_WAIT0();
    __syncthreads();

    // GEMM3 (N=64), warp tile 32x16
    const int wn3 = (wid & 3) * 16;
    float C3[2][2][4];
    #pragma unroll
    for (int i = 0; i < 2; i++)
        #pragma unroll
        for (int j = 0; j < 2; j++)
            #pragma unroll
            for (int q = 0; q < 4; q++) C3[i][j][q] = 0.f;
    #pragma unroll
    for (int c = 0; c < 2; c++)
        mma_chunk<2>(C3, uAh[c], uAl[c],
                     su + M2_OFF_BW + c * 8192, su + M2_OFF_BW + 16384 + c * 8192,
                     wm, wn3, lane);
    __syncthreads();

    // epi3: tanhshrink -> a3 fp32 [64][68] in A region
    {
        float* a3 = (float*)(sm + M2_OFF_A);
        const int r0 = wm + (lane >> 2);
        const int c0 = wn3 + (lane & 3) * 2;
        #pragma unroll
        for (int mt = 0; mt < 2; mt++) {
            #pragma unroll
            for (int nt = 0; nt < 2; nt++) {
                const int n = c0 + nt * 8;
                const float b0v = sb3[n], b1v = sb3[n + 1];
                float v;
                v = C3[mt][nt][0] + b0v; a3[(r0 + mt * 16) * 68 + n]     = v - tanhf(v);
                v = C3[mt][nt][1] + b1v; a3[(r0 + mt * 16) * 68 + n + 1] = v - tanhf(v);
                v = C3[mt][nt][2] + b0v; a3[(r0 + mt * 16 + 8) * 68 + n]     = v - tanhf(v);
                v = C3[mt][nt][3] + b1v; a3[(r0 + mt * 16 + 8) * 68 + n + 1] = v - tanhf(v);
            }
        }
    }
    __syncthreads();

    // layer 4 + sigmoid
    if (tid < 128) {
        const float* a3 = (const float*)(sm + M2_OFF_A);
        const int row = tid >> 1;
        const int c = tid & 1;
        float s = sb4[c];
        #pragma unroll
        for (int k = 0; k < 64; k++) s += a3[row * 68 + k] * sW4[k * 2 + c];
        out[(size_t)(b0 + row) * 2 + c] = 1.f / (1.f + expf(-s));
    }
}

// ---------------- launch ----------------
extern "C" void kernel_launch(void* const* d_in, const int* in_sizes, int n_in,
                              void* d_out, int out_size) {
    const float* x    = (const float*)d_in[0];
    const int*   apps = (const int*)d_in[1];
    const int*   es   = (const int*)d_in[2];
    const int*   ed   = (const int*)d_in[3];
    const float* emb  = (const float*)d_in[4];
    const float* gcw  = (const float*)d_in[5];
    const float* gcb  = (const float*)d_in[6];
    const float* W1   = (const float*)d_in[7];
    const float* b1   = (const float*)d_in[8];
    const float* W2   = (const float*)d_in[9];
    const float* b2   = (const float*)d_in[10];
    const float* W3   = (const float*)d_in[11];
    const float* b3   = (const float*)d_in[12];
    const float* W4   = (const float*)d_in[13];
    const float* b4   = (const float*)d_in[14];
    float* out = (float*)d_out;

    cudaFuncSetAttribute(gemm1_kernel, cudaFuncAttributeMaxDynamicSharedMemorySize, G1_SMEM);
    cudaFuncSetAttribute(mlp2_kernel, cudaFuncAttributeMaxDynamicSharedMemorySize, M2_SMEM);

    prep_kernel<<<512, 256>>>(es, ed, emb, gcw, gcb, W1, W2, W3);
    gconv_kernel<<<B_TOTAL / GC_ROWS, 256>>>(apps);
    gemm1_kernel<<<B_TOTAL / 128, 512, G1_SMEM>>>(x, b1);
    mlp2_kernel<<<B_TOTAL / 64, 256, M2_SMEM>>>(b2, b3, b4, W4, out);
}